// round 6
// baseline (speedup 1.0000x reference)
#include <cuda_runtime.h>
#include <cuda_fp16.h>
#include <math.h>

#define S       64
#define LPREV   512
#define NF      193
#define NFRAMES 100
#define BATCH   64
#define NTH     512
#define NBT     (BATCH * NFRAMES)   // 6400

// ---------------- scratch (static device allocations) ----------------
__device__ float  g_X [NBT * 256];
__device__ float  g_H1[NBT * 256];
__device__ float  g_H2[NBT * 256];
__device__ float  g_C [NBT * 512];
__device__ float  g_fwpre[NBT * 4 * 64];
__device__ int    g_period[NBT];
__device__ __half g_hWsd[128 * 320];
__device__ __half g_hWhh[3 * 192 * 64];

__device__ __forceinline__ float sigm(float x)   { return __fdividef(1.f, 1.f + __expf(-x)); }
__device__ __forceinline__ float tanh_f(float x) { return fmaf(2.f, __fdividef(1.f, 1.f + __expf(-2.f * x)), -1.f); }
__device__ __forceinline__ float red4(float v) {
    v += __shfl_xor_sync(0xffffffffu, v, 1);
    v += __shfl_xor_sync(0xffffffffu, v, 2);
    return v;
}
// dot of 8 fp16 weights (one uint4) with 8 fp32 inputs (two float4)
__device__ __forceinline__ float dot8h(uint4 u, float4 xa, float4 xb) {
    float2 f0 = __half22float2(*reinterpret_cast<__half2*>(&u.x));
    float2 f1 = __half22float2(*reinterpret_cast<__half2*>(&u.y));
    float2 f2 = __half22float2(*reinterpret_cast<__half2*>(&u.z));
    float2 f3 = __half22float2(*reinterpret_cast<__half2*>(&u.w));
    float a = fmaf(f0.x, xa.x, f0.y * xa.y);
    a = fmaf(f1.x, xa.z, a); a = fmaf(f1.y, xa.w, a);
    a = fmaf(f2.x, xb.x, a); a = fmaf(f2.y, xb.y, a);
    a = fmaf(f3.x, xb.z, a); a = fmaf(f3.y, xb.w, a);
    return a;
}
// pack 8 consecutive fp32 -> uint4 of 8 fp16
__device__ __forceinline__ uint4 pack8(const float* __restrict__ s) {
    union { uint4 u; __half2 h[4]; } r;
    r.h[0] = __floats2half2_rn(__ldg(&s[0]), __ldg(&s[1]));
    r.h[1] = __floats2half2_rn(__ldg(&s[2]), __ldg(&s[3]));
    r.h[2] = __floats2half2_rn(__ldg(&s[4]), __ldg(&s[5]));
    r.h[3] = __floats2half2_rn(__ldg(&s[6]), __ldg(&s[7]));
    return r.u;
}
// 64-half dot against 64 fp32 (w8 = 8 uint4 preloaded)
__device__ __forceinline__ float dot64(const uint4* w8, const float* __restrict__ v) {
    const float4* x = (const float4*)v;
    float a0 = 0.f, a1 = 0.f;
    #pragma unroll
    for (int j = 0; j < 8; j += 2) {
        a0 += dot8h(w8[j],     x[2 * j],     x[2 * j + 1]);
        a1 += dot8h(w8[j + 1], x[2 * j + 2], x[2 * j + 3]);
    }
    return a0 + a1;
}
__device__ __forceinline__ void ld8(uint4* d, const uint4* __restrict__ s) {
    #pragma unroll
    for (int j = 0; j < 8; j++) d[j] = __ldg(&s[j]);
}

// ---------------- prep kernels ----------------
__global__ void convert_weights_kernel(const float* __restrict__ Wsd,
                                       const float* __restrict__ Whh1,
                                       const float* __restrict__ Whh2,
                                       const float* __restrict__ Whh3)
{
    int i = blockIdx.x * blockDim.x + threadIdx.x;
    if (i < 128 * 320) g_hWsd[i] = __float2half(Wsd[i]);
    if (i < 12288) {
        g_hWhh[i]         = __float2half(Whh1[i]);
        g_hWhh[12288 + i] = __float2half(Whh2[i]);
        g_hWhh[24576 + i] = __float2half(Whh3[i]);
    }
}

__global__ void build_x_kernel(const float* __restrict__ feats,
                               const float* __restrict__ glob)
{
    const int bt = blockIdx.x;
    const int b = bt / NFRAMES, t = bt % NFRAMES;
    const float* fb = feats + (long)b * NF * NFRAMES;
    for (int i = threadIdx.x; i < 192; i += blockDim.x)
        g_X[bt * 256 + i] = fb[i * NFRAMES + t];
    for (int i = threadIdx.x; i < 64; i += blockDim.x)
        g_X[bt * 256 + 192 + i] = glob[b * 64 + i];
    if (threadIdx.x == 0)
        g_period[bt] = (int)lrintf(fb[192 * NFRAMES + t]);
}

// C[M,N] = tanh(A[M,K] @ W[N,K]^T); tiles 64x64x64
__global__ __launch_bounds__(256)
void gemm_tanh_kernel(const float* __restrict__ Wt, int layer, int N, int K)
{
    const float* A = (layer == 0) ? g_X : (layer == 1) ? g_H1 : g_H2;
    float*       C = (layer == 0) ? g_H1 : (layer == 1) ? g_H2 : g_C;

    __shared__ float As[64][68];
    __shared__ float Ws[64][68];

    const int tid = threadIdx.x;
    const int m0 = blockIdx.y * 64, n0 = blockIdx.x * 64;
    const int lr = tid >> 2, lc = tid & 3;
    const int ty = tid >> 4, tx = tid & 15;

    float acc[4][4] = {};

    for (int k0 = 0; k0 < K; k0 += 64) {
        const float4* Arow = (const float4*)(A  + (long)(m0 + lr) * K + k0);
        const float4* Wrow = (const float4*)(Wt + (long)(n0 + lr) * K + k0);
        #pragma unroll
        for (int jj = 0; jj < 4; jj++) {
            float4 av = __ldg(&Arow[lc * 4 + jj]);
            float4 wv = __ldg(&Wrow[lc * 4 + jj]);
            int kk = lc * 16 + jj * 4;
            As[kk + 0][lr] = av.x; As[kk + 1][lr] = av.y;
            As[kk + 2][lr] = av.z; As[kk + 3][lr] = av.w;
            Ws[kk + 0][lr] = wv.x; Ws[kk + 1][lr] = wv.y;
            Ws[kk + 2][lr] = wv.z; Ws[kk + 3][lr] = wv.w;
        }
        __syncthreads();
        #pragma unroll
        for (int kk = 0; kk < 64; kk++) {
            float4 a = *(const float4*)&As[kk][ty * 4];
            float4 w = *(const float4*)&Ws[kk][tx * 4];
            acc[0][0] = fmaf(a.x, w.x, acc[0][0]); acc[0][1] = fmaf(a.x, w.y, acc[0][1]);
            acc[0][2] = fmaf(a.x, w.z, acc[0][2]); acc[0][3] = fmaf(a.x, w.w, acc[0][3]);
            acc[1][0] = fmaf(a.y, w.x, acc[1][0]); acc[1][1] = fmaf(a.y, w.y, acc[1][1]);
            acc[1][2] = fmaf(a.y, w.z, acc[1][2]); acc[1][3] = fmaf(a.y, w.w, acc[1][3]);
            acc[2][0] = fmaf(a.z, w.x, acc[2][0]); acc[2][1] = fmaf(a.z, w.y, acc[2][1]);
            acc[2][2] = fmaf(a.z, w.z, acc[2][2]); acc[2][3] = fmaf(a.z, w.w, acc[2][3]);
            acc[3][0] = fmaf(a.w, w.x, acc[3][0]); acc[3][1] = fmaf(a.w, w.y, acc[3][1]);
            acc[3][2] = fmaf(a.w, w.z, acc[3][2]); acc[3][3] = fmaf(a.w, w.w, acc[3][3]);
        }
        __syncthreads();
    }
    #pragma unroll
    for (int i = 0; i < 4; i++)
        #pragma unroll
        for (int j = 0; j < 4; j++)
            C[(long)(m0 + ty * 4 + i) * N + n0 + tx * 4 + j] = tanhf(acc[i][j]);
}

// fwpre[bt][k][j] = Wfw[j,0:128] @ feat2s(bt,k) + Wfw[j,260:388] @ sfw(bt,k)
__global__ __launch_bounds__(256)
void fwpre_kernel(const float* __restrict__ Wfw)
{
    const int bt = blockIdx.x;
    const int t  = bt % NFRAMES;
    const int tid = threadIdx.x;
    __shared__ float sc[512], sp[512];
    for (int i = tid; i < 512; i += 256) {
        sc[i] = g_C[(long)bt * 512 + i];
        sp[i] = (t > 0) ? g_C[(long)(bt - 1) * 512 + i] : 0.f;
    }
    __syncthreads();
    const int p = tid & 3, row = tid >> 2;
    const float* wr = Wfw + row * 388;
    #pragma unroll
    for (int k = 0; k < 4; k++) {
        const float* sfw = (k == 0) ? sp : sc;
        const int ksf = (k == 0) ? 3 : (k - 1);
        float acc = 0.f;
        #pragma unroll 8
        for (int mm = 0; mm < 32; mm++) {
            int m = p * 32 + mm;
            acc = fmaf(__ldg(&wr[m]),       sc[4 * m + k],    acc);
            acc = fmaf(__ldg(&wr[260 + m]), sfw[4 * m + ksf], acc);
        }
        acc += __shfl_xor_sync(0xffffffffu, acc, 1);
        acc += __shfl_xor_sync(0xffffffffu, acc, 2);
        if (p == 0) g_fwpre[((long)bt * 4 + k) * 64 + row] = acc;
    }
}

// ---------------- serial recurrence ----------------

// dynamic smem: Wih x3 (fp16) + Wsg (fp16) + Wout (fp16) + Wfw2 (fp16, 64x160)
#define DYN_H16   (3 * 192 * 128 + 128 * 128 + 64 * 128 + 64 * 160)   // 108544 halfs
#define DYN_BYTES (DYN_H16 * 2)                                       // 217088 B

__global__ __launch_bounds__(NTH, 1)
void fargan_kernel(const float* __restrict__ prev0,
                   const float* __restrict__ Wfw,     // (64,388)
                   const float* __restrict__ Wfw_g,   // (64,64)
                   const float* __restrict__ Wih1,    // (192,128)
                   const float* __restrict__ Wih2,
                   const float* __restrict__ Wih3,
                   const float* __restrict__ Wg1,     // (64,64)
                   const float* __restrict__ Wg2,
                   const float* __restrict__ Wg3,
                   const float* __restrict__ Wsg,     // (128,128)
                   const float* __restrict__ Wout,    // (64,128)
                   float* __restrict__ outp)          // (B, 25600)
{
    const int b   = blockIdx.x;
    const int tid = threadIdx.x;
    const int p   = tid & 3;        // 4 threads per row (main half)
    const int r0  = tid >> 2;       // row 0..63 for main threads (tid<256)
    const int s   = tid - 256;      // side-thread index 0..255

    extern __shared__ __half dynh[];
    __half* sWih  = dynh;                    // 3 x 192 x 128
    __half* sWsg  = sWih + 3 * 192 * 128;    // 128 x 128
    __half* sWout = sWsg + 128 * 128;        // 64 x 128
    __half* sWfw2 = sWout + 64 * 128;        // 64 x 160 (cols 128..259 of Wfw, padded)

    __shared__ __align__(16) float ring[LPREV];
    __shared__ __align__(16) float stbuf[2][3][S];
    __shared__ __align__(16) float fwp4[256];
    __shared__ __align__(16) float subin[160];
    __shared__ __align__(16) float fwv[S];
    __shared__ __align__(16) float xcat[2 * S];
    __shared__ __align__(16) float psub[S];
    __shared__ __align__(16) float fwf[S];
    __shared__ __align__(16) float ov[3][S];
    __shared__ __align__(16) float sdv[2 * S];
    __shared__ __align__(16) float sov[2 * S];
    __shared__ __align__(16) float ghs[3 * 192];
    __shared__ int period_sh;

    // ---- one-time smem staging (fp16) ----
    {
        const float* src[3] = { Wih1, Wih2, Wih3 };
        #pragma unroll
        for (int m = 0; m < 3; m++)
            for (int i = tid; i < 192 * 128; i += NTH)
                sWih[m * 192 * 128 + i] = __float2half(__ldg(&src[m][i]));
        for (int i = tid; i < 128 * 128; i += NTH)
            sWsg[i] = __float2half(__ldg(&Wsg[i]));
        for (int i = tid; i < 64 * 128; i += NTH)
            sWout[i] = __float2half(__ldg(&Wout[i]));
        for (int i = tid; i < 64 * 160; i += NTH) {
            int row = i / 160, col = i % 160;
            sWfw2[i] = (col < 132) ? __float2half(__ldg(&Wfw[row * 388 + 128 + col])) : __half(0.f);
        }
    }

    // ---- main-thread register gates: Wg1,Wg2,Wg3,Wfwg rows r0, cols [16p,16p+16) ----
    uint4 rgate[4][2];
    if (tid < 256) {
        const float* gsrc[4] = { Wg1, Wg2, Wg3, Wfw_g };
        #pragma unroll
        for (int m = 0; m < 4; m++) {
            rgate[m][0] = pack8(gsrc[m] + r0 * 64 + 16 * p);
            rgate[m][1] = pack8(gsrc[m] + r0 * 64 + 16 * p + 8);
        }
    }

    // ---- side-thread double-buffered weight rows ----
    uint4 wX[8], wY[8];
    float sdp = 0.f;

    // ---- init state ----
    for (int i = tid; i < LPREV; i += NTH) ring[i] = prev0[b * LPREV + i];
    if (tid < 3 * S) stbuf[0][tid >> 6][tid & 63] = 0.f;
    if (tid >= 132 && tid < 160) subin[tid] = 0.f;   // static pad
    int head = 0;
    int pb = 0;
    __syncthreads();

    for (int tf = 0; tf < NFRAMES; tf++) {
        const int bt = b * NFRAMES + tf;
        // ---- frame top: stage fwpre for all 4 subframes + period ----
        if (tid < 256) fwp4[tid] = __ldg(&g_fwpre[(long)bt * 256 + tid]);
        if (tid == 0) period_sh = __ldg(&g_period[bt]);
        __syncthreads();
        const int period = period_sh;

        for (int k = 0; k < 4; k++) {
            // ================= stage A =================
            if (tid < 160) {
                if (tid < 64) {
                    float v = ring[(head + 448 + tid) & 511];
                    subin[tid] = v;
                    psub[tid] = v;
                    xcat[64 + tid] = v;
                } else if (tid < 132) {
                    int i = tid - 64;
                    int idx = LPREV - period + i - 2;
                    if (idx >= LPREV) idx -= period;
                    subin[tid] = ring[(head + idx) & 511];
                }
            } else if (tid >= 256 && s < 192) {
                ld8(wX, (const uint4*)(g_hWhh + s * 64));             // Whh1 row s
            }
            __syncthreads();

            // ================= stage B: fwraw =================
            float fwreg = 0.f;
            if (tid < 256) {
                const uint4* w = (const uint4*)(sWfw2 + r0 * 160);
                const float4* xs = (const float4*)subin;
                float a = 0.f;
                #pragma unroll
                for (int jj = 0; jj < 5; jj++) {
                    int j = p + 4 * jj;
                    a += dot8h(w[j], xs[2 * j], xs[2 * j + 1]);
                }
                a = red4(a);
                fwreg = tanh_f(a + fwp4[k * 64 + r0]);
                if (p == 0) fwv[r0] = fwreg;
            } else if (s < 192) {
                ghs[s] = dot64(wX, stbuf[pb][0]);                     // gh1
                ld8(wY, (const uint4*)(g_hWhh + (192 + s) * 64));     // Whh2
            }
            __syncthreads();

            // ================= stage C: GLU gate on fw =================
            if (tid < 256) {
                const float4* xs = (const float4*)fwv;
                float a = dot8h(rgate[3][0], xs[4 * p], xs[4 * p + 1])
                        + dot8h(rgate[3][1], xs[4 * p + 2], xs[4 * p + 3]);
                a = red4(a);
                fwreg = fwreg * sigm(a);
                if (p == 0) { fwf[r0] = fwreg; xcat[r0] = fwreg; }
            } else if (s < 192) {
                ghs[192 + s] = dot64(wY, stbuf[pb][1]);               // gh2
                ld8(wX, (const uint4*)(g_hWhh + (384 + s) * 64));     // Whh3
            }
            __syncthreads();

            // ================= 3 x (GRU, GLU) =================
            const uint4* wsd = (const uint4*)(g_hWsd + (s < 128 ? s : 0) * 320);
            float streg = 0.f;
            #pragma unroll
            for (int L = 0; L < 3; L++) {
                // ---- GRU_L ----
                if (tid < 256) {
                    const __half* WI = sWih + L * 192 * 128;
                    const float4* xs = (const float4*)xcat;
                    float gi0 = 0.f, gi1 = 0.f, gi2 = 0.f;
                    {
                        const uint4* w = (const uint4*)(WI + r0 * 128);
                        #pragma unroll
                        for (int jj = 0; jj < 4; jj++) { int j = p + 4 * jj; gi0 += dot8h(w[j], xs[2 * j], xs[2 * j + 1]); }
                    }
                    {
                        const uint4* w = (const uint4*)(WI + (r0 + 64) * 128);
                        #pragma unroll
                        for (int jj = 0; jj < 4; jj++) { int j = p + 4 * jj; gi1 += dot8h(w[j], xs[2 * j], xs[2 * j + 1]); }
                    }
                    {
                        const uint4* w = (const uint4*)(WI + (r0 + 128) * 128);
                        #pragma unroll
                        for (int jj = 0; jj < 4; jj++) { int j = p + 4 * jj; gi2 += dot8h(w[j], xs[2 * j], xs[2 * j + 1]); }
                    }
                    gi0 = red4(gi0); gi1 = red4(gi1); gi2 = red4(gi2);
                    float g0 = ghs[L * 192 + r0];
                    float g1 = ghs[L * 192 + 64 + r0];
                    float g2 = ghs[L * 192 + 128 + r0];
                    float r = sigm(gi0 + g0);
                    float z = sigm(gi1 + g1);
                    float n = tanh_f(gi2 + r * g2);
                    streg = (1.f - z) * n + z * stbuf[pb][L][r0];
                    if (p == 0) stbuf[pb ^ 1][L][r0] = streg;
                } else {
                    if (L == 0) {
                        if (s < 192) ghs[384 + s] = dot64(wX, stbuf[pb][2]);   // gh3
                        if (s < 128) ld8(wY, wsd + 32);                        // Wsd psub cols
                    } else if (L == 1) {
                        if (s < 128) { sdp += dot64(wX, fwf); ld8(wY, wsd + 0); }   // fw part; load o1 cols
                    } else {
                        if (s < 128) { sdp += dot64(wX, ov[1]); ld8(wY, wsd + 16); } // o2 part; load o3 cols
                    }
                }
                __syncthreads();

                // ---- GLU_L ----
                if (tid < 256) {
                    const float4* xs = (const float4*)stbuf[pb ^ 1][L];
                    float a = dot8h(rgate[L][0], xs[4 * p], xs[4 * p + 1])
                            + dot8h(rgate[L][1], xs[4 * p + 2], xs[4 * p + 3]);
                    a = red4(a);
                    float v = streg * sigm(a);
                    if (p == 0) {
                        ov[L][r0] = v;
                        if (L < 2) xcat[r0] = v;
                    }
                } else if (s < 128) {
                    if (L == 0)      { sdp  = dot64(wY, psub);  ld8(wX, wsd + 24); } // psub part; load fw cols
                    else if (L == 1) { sdp += dot64(wY, ov[0]); ld8(wX, wsd + 8);  } // o1 part; load o2 cols
                    // L == 2: idle (o3 being written this stage)
                }
                __syncthreads();
            }

            // ================= stage J: finalize sdv (side only) =================
            if (tid >= 256 && s < 128) {
                sdv[s] = tanh_f(sdp + dot64(wY, ov[2]));
                sdp = 0.f;
            }
            __syncthreads();

            // ================= stage K: sov = sdv * sigm(Wsg @ sdv) =================
            if (tid < 256) {
                const float4* xs = (const float4*)sdv;
                #pragma unroll
                for (int it = 0; it < 2; it++) {
                    const uint4* w = (const uint4*)(sWsg + (r0 + 64 * it) * 128);
                    float a = 0.f;
                    #pragma unroll
                    for (int jj = 0; jj < 4; jj++) { int j = p + 4 * jj; a += dot8h(w[j], xs[2 * j], xs[2 * j + 1]); }
                    a = red4(a);
                    if (p == 0) sov[r0 + 64 * it] = sdv[r0 + 64 * it] * sigm(a);
                }
            }
            __syncthreads();

            // ================= stage L: out = tanh(Wout @ sov); emit =================
            if (tid < 256) {
                const float4* xs = (const float4*)sov;
                const uint4* w = (const uint4*)(sWout + r0 * 128);
                float a = 0.f;
                #pragma unroll
                for (int jj = 0; jj < 4; jj++) { int j = p + 4 * jj; a += dot8h(w[j], xs[2 * j], xs[2 * j + 1]); }
                a = red4(a);
                float out = tanh_f(a);
                if (p == 0) {
                    outp[(long)b * (NFRAMES * 4 * S) + tf * (4 * S) + k * S + r0] = out;
                    ring[(head + r0) & 511] = out;
                }
            }
            head = (head + 64) & 511;
            pb ^= 1;
            __syncthreads();
        }
    }
}

extern "C" void kernel_launch(void* const* d_in, const int* in_sizes, int n_in,
                              void* d_out, int out_size)
{
    const float* feats = (const float*)d_in[0];
    const float* glob  = (const float*)d_in[1];
    const float* prev0 = (const float*)d_in[2];
    const float* Wc1   = (const float*)d_in[3];
    const float* Wc2   = (const float*)d_in[4];
    const float* Wc3   = (const float*)d_in[5];
    const float* Wfw   = (const float*)d_in[6];
    const float* Wfw_g = (const float*)d_in[7];
    const float* Wih1  = (const float*)d_in[8];
    const float* Whh1  = (const float*)d_in[9];
    const float* Wih2  = (const float*)d_in[10];
    const float* Whh2  = (const float*)d_in[11];
    const float* Wih3  = (const float*)d_in[12];
    const float* Whh3  = (const float*)d_in[13];
    const float* Wg1   = (const float*)d_in[14];
    const float* Wg2   = (const float*)d_in[15];
    const float* Wg3   = (const float*)d_in[16];
    const float* Wsg   = (const float*)d_in[17];
    const float* Wsd   = (const float*)d_in[18];
    const float* Wout  = (const float*)d_in[19];
    float* outp = (float*)d_out;

    static bool attr_set = false;
    if (!attr_set) {
        cudaFuncSetAttribute(fargan_kernel,
                             cudaFuncAttributeMaxDynamicSharedMemorySize, DYN_BYTES);
        attr_set = true;
    }

    convert_weights_kernel<<<(128 * 320 + 255) / 256, 256>>>(Wsd, Whh1, Whh2, Whh3);
    build_x_kernel<<<NBT, 64>>>(feats, glob);
    gemm_tanh_kernel<<<dim3(4, 100), 256>>>(Wc1, 0, 256, 256);
    gemm_tanh_kernel<<<dim3(4, 100), 256>>>(Wc2, 1, 256, 256);
    gemm_tanh_kernel<<<dim3(8, 100), 256>>>(Wc3, 2, 512, 256);
    fwpre_kernel<<<NBT, 256>>>(Wfw);
    fargan_kernel<<<BATCH, NTH, DYN_BYTES>>>(prev0,
                                  Wfw, Wfw_g,
                                  Wih1, Wih2, Wih3,
                                  Wg1, Wg2, Wg3, Wsg, Wout, outp);
}

// round 7
// speedup vs baseline: 1.4654x; 1.4654x over previous
#include <cuda_runtime.h>
#include <cuda_fp16.h>
#include <math.h>

#define S       64
#define LPREV   512
#define NF      193
#define NFRAMES 100
#define BATCH   64
#define NTH     512
#define NBT     (BATCH * NFRAMES)   // 6400

// ---------------- scratch (static device allocations) ----------------
__device__ float  g_X [NBT * 256];
__device__ float  g_H1[NBT * 256];
__device__ float  g_H2[NBT * 256];
__device__ float  g_C [NBT * 512];
__device__ float  g_fwpre[NBT * 4 * 64];
__device__ int    g_period[NBT];
__device__ __half g_hWsd[128 * 320];

__device__ __forceinline__ float sigm(float x)   { return __fdividef(1.f, 1.f + __expf(-x)); }
__device__ __forceinline__ float tanh_f(float x) { return fmaf(2.f, __fdividef(1.f, 1.f + __expf(-2.f * x)), -1.f); }
__device__ __forceinline__ float red8(float v) {
    v += __shfl_xor_sync(0xffffffffu, v, 1);
    v += __shfl_xor_sync(0xffffffffu, v, 2);
    v += __shfl_xor_sync(0xffffffffu, v, 4);
    return v;
}
// convert 8 fp16 (uint4) once, FMA into two sequences' accumulators
__device__ __forceinline__ void dot8h_dual(uint4 u,
                                           float4 xa0, float4 xb0,
                                           float4 xa1, float4 xb1,
                                           float& a0, float& a1)
{
    float2 f0 = __half22float2(*reinterpret_cast<__half2*>(&u.x));
    float2 f1 = __half22float2(*reinterpret_cast<__half2*>(&u.y));
    float2 f2 = __half22float2(*reinterpret_cast<__half2*>(&u.z));
    float2 f3 = __half22float2(*reinterpret_cast<__half2*>(&u.w));
    a0 = fmaf(f0.x, xa0.x, a0); a0 = fmaf(f0.y, xa0.y, a0);
    a0 = fmaf(f1.x, xa0.z, a0); a0 = fmaf(f1.y, xa0.w, a0);
    a0 = fmaf(f2.x, xb0.x, a0); a0 = fmaf(f2.y, xb0.y, a0);
    a0 = fmaf(f3.x, xb0.z, a0); a0 = fmaf(f3.y, xb0.w, a0);
    a1 = fmaf(f0.x, xa1.x, a1); a1 = fmaf(f0.y, xa1.y, a1);
    a1 = fmaf(f1.x, xa1.z, a1); a1 = fmaf(f1.y, xa1.w, a1);
    a1 = fmaf(f2.x, xb1.x, a1); a1 = fmaf(f2.y, xb1.y, a1);
    a1 = fmaf(f3.x, xb1.z, a1); a1 = fmaf(f3.y, xb1.w, a1);
}
// pack 8 consecutive fp32 -> uint4 of 8 fp16
__device__ __forceinline__ uint4 pack8(const float* __restrict__ s) {
    union { uint4 u; __half2 h[4]; } r;
    r.h[0] = __floats2half2_rn(__ldg(&s[0]), __ldg(&s[1]));
    r.h[1] = __floats2half2_rn(__ldg(&s[2]), __ldg(&s[3]));
    r.h[2] = __floats2half2_rn(__ldg(&s[4]), __ldg(&s[5]));
    r.h[3] = __floats2half2_rn(__ldg(&s[6]), __ldg(&s[7]));
    return r.u;
}

// ---------------- prep kernels ----------------
__global__ void convert_wsd_kernel(const float* __restrict__ Wsd)
{
    int i = blockIdx.x * blockDim.x + threadIdx.x;
    if (i < 128 * 320) g_hWsd[i] = __float2half(Wsd[i]);
}

__global__ void build_x_kernel(const float* __restrict__ feats,
                               const float* __restrict__ glob)
{
    const int bt = blockIdx.x;
    const int b = bt / NFRAMES, t = bt % NFRAMES;
    const float* fb = feats + (long)b * NF * NFRAMES;
    for (int i = threadIdx.x; i < 192; i += blockDim.x)
        g_X[bt * 256 + i] = fb[i * NFRAMES + t];
    for (int i = threadIdx.x; i < 64; i += blockDim.x)
        g_X[bt * 256 + 192 + i] = glob[b * 64 + i];
    if (threadIdx.x == 0)
        g_period[bt] = (int)lrintf(fb[192 * NFRAMES + t]);
}

// C[M,N] = tanh(A[M,K] @ W[N,K]^T); tiles 64x64x64
__global__ __launch_bounds__(256)
void gemm_tanh_kernel(const float* __restrict__ Wt, int layer, int N, int K)
{
    const float* A = (layer == 0) ? g_X : (layer == 1) ? g_H1 : g_H2;
    float*       C = (layer == 0) ? g_H1 : (layer == 1) ? g_H2 : g_C;

    __shared__ float As[64][68];
    __shared__ float Ws[64][68];

    const int tid = threadIdx.x;
    const int m0 = blockIdx.y * 64, n0 = blockIdx.x * 64;
    const int lr = tid >> 2, lc = tid & 3;
    const int ty = tid >> 4, tx = tid & 15;

    float acc[4][4] = {};

    for (int k0 = 0; k0 < K; k0 += 64) {
        const float4* Arow = (const float4*)(A  + (long)(m0 + lr) * K + k0);
        const float4* Wrow = (const float4*)(Wt + (long)(n0 + lr) * K + k0);
        #pragma unroll
        for (int jj = 0; jj < 4; jj++) {
            float4 av = __ldg(&Arow[lc * 4 + jj]);
            float4 wv = __ldg(&Wrow[lc * 4 + jj]);
            int kk = lc * 16 + jj * 4;
            As[kk + 0][lr] = av.x; As[kk + 1][lr] = av.y;
            As[kk + 2][lr] = av.z; As[kk + 3][lr] = av.w;
            Ws[kk + 0][lr] = wv.x; Ws[kk + 1][lr] = wv.y;
            Ws[kk + 2][lr] = wv.z; Ws[kk + 3][lr] = wv.w;
        }
        __syncthreads();
        #pragma unroll
        for (int kk = 0; kk < 64; kk++) {
            float4 a = *(const float4*)&As[kk][ty * 4];
            float4 w = *(const float4*)&Ws[kk][tx * 4];
            acc[0][0] = fmaf(a.x, w.x, acc[0][0]); acc[0][1] = fmaf(a.x, w.y, acc[0][1]);
            acc[0][2] = fmaf(a.x, w.z, acc[0][2]); acc[0][3] = fmaf(a.x, w.w, acc[0][3]);
            acc[1][0] = fmaf(a.y, w.x, acc[1][0]); acc[1][1] = fmaf(a.y, w.y, acc[1][1]);
            acc[1][2] = fmaf(a.y, w.z, acc[1][2]); acc[1][3] = fmaf(a.y, w.w, acc[1][3]);
            acc[2][0] = fmaf(a.z, w.x, acc[2][0]); acc[2][1] = fmaf(a.z, w.y, acc[2][1]);
            acc[2][2] = fmaf(a.z, w.z, acc[2][2]); acc[2][3] = fmaf(a.z, w.w, acc[2][3]);
            acc[3][0] = fmaf(a.w, w.x, acc[3][0]); acc[3][1] = fmaf(a.w, w.y, acc[3][1]);
            acc[3][2] = fmaf(a.w, w.z, acc[3][2]); acc[3][3] = fmaf(a.w, w.w, acc[3][3]);
        }
        __syncthreads();
    }
    #pragma unroll
    for (int i = 0; i < 4; i++)
        #pragma unroll
        for (int j = 0; j < 4; j++)
            C[(long)(m0 + ty * 4 + i) * N + n0 + tx * 4 + j] = tanhf(acc[i][j]);
}

// fwpre[bt][k][j] = Wfw[j,0:128] @ feat2s(bt,k) + Wfw[j,260:388] @ sfw(bt,k)
__global__ __launch_bounds__(256)
void fwpre_kernel(const float* __restrict__ Wfw)
{
    const int bt = blockIdx.x;
    const int t  = bt % NFRAMES;
    const int tid = threadIdx.x;
    __shared__ float sc[512], sp[512];
    for (int i = tid; i < 512; i += 256) {
        sc[i] = g_C[(long)bt * 512 + i];
        sp[i] = (t > 0) ? g_C[(long)(bt - 1) * 512 + i] : 0.f;
    }
    __syncthreads();
    const int p = tid & 3, row = tid >> 2;
    const float* wr = Wfw + row * 388;
    #pragma unroll
    for (int k = 0; k < 4; k++) {
        const float* sfw = (k == 0) ? sp : sc;
        const int ksf = (k == 0) ? 3 : (k - 1);
        float acc = 0.f;
        #pragma unroll 8
        for (int mm = 0; mm < 32; mm++) {
            int m = p * 32 + mm;
            acc = fmaf(__ldg(&wr[m]),       sc[4 * m + k],    acc);
            acc = fmaf(__ldg(&wr[260 + m]), sfw[4 * m + ksf], acc);
        }
        acc += __shfl_xor_sync(0xffffffffu, acc, 1);
        acc += __shfl_xor_sync(0xffffffffu, acc, 2);
        if (p == 0) g_fwpre[((long)bt * 4 + k) * 64 + row] = acc;
    }
}

// ---------------- serial recurrence: 2 batch sequences per block ----------------

// dynamic smem: Wih x3 + Wsg + Wout, all fp16
#define DYN_H16   (3 * 192 * 128 + 128 * 128 + 64 * 128)   // 98304 halfs
#define DYN_BYTES (DYN_H16 * 2)                            // 196608 B

__global__ __launch_bounds__(NTH, 1)
void fargan_kernel(const float* __restrict__ prev0,
                   const float* __restrict__ Wfw,     // (64,388)
                   const float* __restrict__ Wfw_g,   // (64,64)
                   const float* __restrict__ Wih1,    // (192,128)
                   const float* __restrict__ Whh1,    // (192,64)
                   const float* __restrict__ Wih2,
                   const float* __restrict__ Whh2,
                   const float* __restrict__ Wih3,
                   const float* __restrict__ Whh3,
                   const float* __restrict__ Wg1,     // (64,64)
                   const float* __restrict__ Wg2,
                   const float* __restrict__ Wg3,
                   const float* __restrict__ Wsg,     // (128,128)
                   const float* __restrict__ Wout,    // (64,128)
                   float* __restrict__ outp)          // (B, 25600)
{
    const int tid = threadIdx.x;
    const int p   = tid & 7;        // 8 threads per row
    const int r0  = tid >> 3;       // row 0..63
    const int b0  = 2 * blockIdx.x;

    extern __shared__ __half dynh[];
    __half* sWih  = dynh;                    // 3 x 192 x 128
    __half* sWsg  = sWih + 3 * 192 * 128;    // 128 x 128
    __half* sWout = sWsg + 128 * 128;        // 64 x 128

    __shared__ __align__(16) float ring[2][LPREV];
    __shared__ __align__(16) float stbuf[2][2][3][S];   // [q][pb][layer][row]
    __shared__ __align__(16) float subin[2][160];       // [prev(64)|lookback(68)|pad]
    __shared__ __align__(16) float fwv[2][S];
    __shared__ __align__(16) float xcat[2][2 * S];
    __shared__ __align__(16) float skip[2][5 * S];
    __shared__ __align__(16) float sdv[2][2 * S];
    __shared__ __align__(16) float sov[2][2 * S];
    __shared__ __align__(16) float fwp4[2][256];
    __shared__ int period_sh[2];

    // ---- one-time smem staging (fp16) ----
    {
        const float* src[3] = { Wih1, Wih2, Wih3 };
        #pragma unroll
        for (int m = 0; m < 3; m++)
            for (int i = tid; i < 192 * 128; i += NTH)
                sWih[m * 192 * 128 + i] = __float2half(__ldg(&src[m][i]));
        for (int i = tid; i < 128 * 128; i += NTH)
            sWsg[i] = __float2half(__ldg(&Wsg[i]));
        for (int i = tid; i < 64 * 128; i += NTH)
            sWout[i] = __float2half(__ldg(&Wout[i]));
    }

    // ---- persistent register weights ----
    // Whh x3: rows r0+64*it, cols [8p, 8p+8)  (fp16, 36 regs)
    uint4 rwhh[3][3];
    {
        const float* src[3] = { Whh1, Whh2, Whh3 };
        #pragma unroll
        for (int m = 0; m < 3; m++)
            #pragma unroll
            for (int it = 0; it < 3; it++)
                rwhh[m][it] = pack8(src[m] + (r0 + 64 * it) * 64 + 8 * p);
    }
    // gates Wg1..3 + Wfwg: row r0, cols [8p, 8p+8)  (16 regs)
    uint4 rgate[4];
    {
        const float* gsrc[4] = { Wg1, Wg2, Wg3, Wfw_g };
        #pragma unroll
        for (int m = 0; m < 4; m++) rgate[m] = pack8(gsrc[m] + r0 * 64 + 8 * p);
    }
    // Wfw cols [128,264): row r0, 17 consecutive fp32 (17 regs)
    float rfw2[17];
    #pragma unroll
    for (int i = 0; i < 17; i++) {
        int col = p * 17 + i;
        rfw2[i] = (col < 132) ? __ldg(&Wfw[r0 * 388 + 128 + col]) : 0.f;
    }

    // ---- init state ----
    for (int i = tid; i < 2 * LPREV; i += NTH)
        ring[i >> 9][i & 511] = prev0[(b0 + (i >> 9)) * LPREV + (i & 511)];
    for (int i = tid; i < 2 * 2 * 3 * S; i += NTH)
        ((float*)stbuf)[i] = 0.f;
    if (tid < 2 * 28) subin[tid / 28][132 + (tid % 28)] = 0.f;
    int head = 0;
    int pb = 0;
    __syncthreads();

    for (int tf = 0; tf < NFRAMES; tf++) {
        // ---- frame top: stage fwpre (4 subframes) + period, both sequences ----
        {
            const int q = tid >> 8, i = tid & 255;
            const int bt = (b0 + q) * NFRAMES + tf;
            fwp4[q][i] = __ldg(&g_fwpre[(long)bt * 256 + i]);
            if (i == 0) period_sh[q] = __ldg(&g_period[bt]);
        }
        __syncthreads();

        for (int k = 0; k < 4; k++) {
            // ================= stage A: inputs for both sequences =================
            {
                const int q = tid >> 8, i = tid & 255;
                if (i < 64) {
                    float v = ring[q][(head + 448 + i) & 511];
                    subin[q][i] = v;
                    skip[q][256 + i] = v;
                    xcat[q][64 + i] = v;
                } else if (i < 132) {
                    int j = i - 64;
                    int idx = LPREV - period_sh[q] + j - 2;
                    if (idx >= LPREV) idx -= period_sh[q];
                    subin[q][i] = ring[q][(head + idx) & 511];
                }
            }
            __syncthreads();

            // ================= stage B: fwraw (register fp32 weights) =================
            float fw0, fw1;
            {
                float a0 = 0.f, a1 = 0.f;
                #pragma unroll
                for (int i = 0; i < 17; i++) {
                    int c = p * 17 + i;
                    a0 = fmaf(rfw2[i], subin[0][c], a0);
                    a1 = fmaf(rfw2[i], subin[1][c], a1);
                }
                a0 = red8(a0); a1 = red8(a1);
                fw0 = tanh_f(a0 + fwp4[0][k * 64 + r0]);
                fw1 = tanh_f(a1 + fwp4[1][k * 64 + r0]);
                if (p == 0) { fwv[0][r0] = fw0; fwv[1][r0] = fw1; }
            }
            __syncthreads();

            // ================= stage C: GLU gate on fw =================
            {
                const float4* x0 = (const float4*)fwv[0];
                const float4* x1 = (const float4*)fwv[1];
                float a0 = 0.f, a1 = 0.f;
                dot8h_dual(rgate[3], x0[2 * p], x0[2 * p + 1], x1[2 * p], x1[2 * p + 1], a0, a1);
                a0 = red8(a0); a1 = red8(a1);
                fw0 *= sigm(a0); fw1 *= sigm(a1);
                if (p == 0) {
                    xcat[0][r0] = fw0; skip[0][192 + r0] = fw0;
                    xcat[1][r0] = fw1; skip[1][192 + r0] = fw1;
                }
            }
            __syncthreads();

            // ================= 3 x (GRU fused + GLU fused) =================
            #pragma unroll
            for (int L = 0; L < 3; L++) {
                const __half* WI = sWih + L * 192 * 128;
                float st0, st1;
                {
                    const float4* x0 = (const float4*)xcat[0];
                    const float4* x1 = (const float4*)xcat[1];
                    const float4* s0 = (const float4*)stbuf[0][pb][L];
                    const float4* s1 = (const float4*)stbuf[1][pb][L];
                    float gi0[3], gi1[3], gh0[3], gh1[3];
                    #pragma unroll
                    for (int it = 0; it < 3; it++) {
                        const uint4* w = (const uint4*)(WI + (r0 + (it << 6)) * 128);
                        float a0 = 0.f, a1 = 0.f;
                        dot8h_dual(w[p],     x0[2 * p],      x0[2 * p + 1],
                                             x1[2 * p],      x1[2 * p + 1],  a0, a1);
                        dot8h_dual(w[p + 8], x0[2 * p + 16], x0[2 * p + 17],
                                             x1[2 * p + 16], x1[2 * p + 17], a0, a1);
                        gi0[it] = red8(a0); gi1[it] = red8(a1);
                        float b0a = 0.f, b1a = 0.f;
                        dot8h_dual(rwhh[L][it], s0[2 * p], s0[2 * p + 1],
                                                s1[2 * p], s1[2 * p + 1], b0a, b1a);
                        gh0[it] = red8(b0a); gh1[it] = red8(b1a);
                    }
                    {
                        float r = sigm(gi0[0] + gh0[0]);
                        float z = sigm(gi0[1] + gh0[1]);
                        float n = tanh_f(gi0[2] + r * gh0[2]);
                        st0 = (1.f - z) * n + z * stbuf[0][pb][L][r0];
                    }
                    {
                        float r = sigm(gi1[0] + gh1[0]);
                        float z = sigm(gi1[1] + gh1[1]);
                        float n = tanh_f(gi1[2] + r * gh1[2]);
                        st1 = (1.f - z) * n + z * stbuf[1][pb][L][r0];
                    }
                    if (p == 0) { stbuf[0][pb ^ 1][L][r0] = st0; stbuf[1][pb ^ 1][L][r0] = st1; }
                }
                __syncthreads();
                {
                    const float4* x0 = (const float4*)stbuf[0][pb ^ 1][L];
                    const float4* x1 = (const float4*)stbuf[1][pb ^ 1][L];
                    float a0 = 0.f, a1 = 0.f;
                    dot8h_dual(rgate[L], x0[2 * p], x0[2 * p + 1], x1[2 * p], x1[2 * p + 1], a0, a1);
                    a0 = red8(a0); a1 = red8(a1);
                    float v0 = st0 * sigm(a0), v1 = st1 * sigm(a1);
                    if (p == 0) {
                        skip[0][64 * L + r0] = v0;
                        skip[1][64 * L + r0] = v1;
                        if (L < 2) { xcat[0][r0] = v0; xcat[1][r0] = v1; }
                    }
                }
                __syncthreads();
            }

            // ================= stage J: sdv = tanh(Wsd @ skip) (L2 fp16, dual) =================
            float sdva0[2], sdva1[2];
            {
                const float4* x0 = (const float4*)skip[0];
                const float4* x1 = (const float4*)skip[1];
                #pragma unroll
                for (int it = 0; it < 2; it++) {
                    const uint4* w = (const uint4*)(g_hWsd + (r0 + (it << 6)) * 320);
                    float a0 = 0.f, a1 = 0.f;
                    #pragma unroll
                    for (int j = 0; j < 5; j++) {
                        int c = p + 8 * j;
                        dot8h_dual(__ldg(&w[c]), x0[2 * c], x0[2 * c + 1],
                                                 x1[2 * c], x1[2 * c + 1], a0, a1);
                    }
                    sdva0[it] = tanh_f(red8(a0));
                    sdva1[it] = tanh_f(red8(a1));
                    if (p == 0) { sdv[0][r0 + 64 * it] = sdva0[it]; sdv[1][r0 + 64 * it] = sdva1[it]; }
                }
            }
            __syncthreads();

            // ================= stage K: sov = sdv * sigm(Wsg @ sdv) (smem fp16) =================
            {
                const float4* x0 = (const float4*)sdv[0];
                const float4* x1 = (const float4*)sdv[1];
                #pragma unroll
                for (int it = 0; it < 2; it++) {
                    const uint4* w = (const uint4*)(sWsg + (r0 + (it << 6)) * 128);
                    float a0 = 0.f, a1 = 0.f;
                    dot8h_dual(w[p],     x0[2 * p],      x0[2 * p + 1],
                                         x1[2 * p],      x1[2 * p + 1],  a0, a1);
                    dot8h_dual(w[p + 8], x0[2 * p + 16], x0[2 * p + 17],
                                         x1[2 * p + 16], x1[2 * p + 17], a0, a1);
                    a0 = red8(a0); a1 = red8(a1);
                    if (p == 0) {
                        sov[0][r0 + 64 * it] = sdva0[it] * sigm(a0);
                        sov[1][r0 + 64 * it] = sdva1[it] * sigm(a1);
                    }
                }
            }
            __syncthreads();

            // ================= stage L: out = tanh(Wout @ sov); emit (smem fp16) =================
            {
                const float4* x0 = (const float4*)sov[0];
                const float4* x1 = (const float4*)sov[1];
                const uint4* w = (const uint4*)(sWout + r0 * 128);
                float a0 = 0.f, a1 = 0.f;
                dot8h_dual(w[p],     x0[2 * p],      x0[2 * p + 1],
                                     x1[2 * p],      x1[2 * p + 1],  a0, a1);
                dot8h_dual(w[p + 8], x0[2 * p + 16], x0[2 * p + 17],
                                     x1[2 * p + 16], x1[2 * p + 17], a0, a1);
                float o0 = tanh_f(red8(a0));
                float o1 = tanh_f(red8(a1));
                if (p == 0) {
                    outp[(long)b0 * 25600 + tf * 256 + k * 64 + r0] = o0;
                    outp[(long)(b0 + 1) * 25600 + tf * 256 + k * 64 + r0] = o1;
                    ring[0][(head + r0) & 511] = o0;
                    ring[1][(head + r0) & 511] = o1;
                }
            }
            head = (head + 64) & 511;
            pb ^= 1;
            __syncthreads();
        }
    }
}

extern "C" void kernel_launch(void* const* d_in, const int* in_sizes, int n_in,
                              void* d_out, int out_size)
{
    const float* feats = (const float*)d_in[0];
    const float* glob  = (const float*)d_in[1];
    const float* prev0 = (const float*)d_in[2];
    const float* Wc1   = (const float*)d_in[3];
    const float* Wc2   = (const float*)d_in[4];
    const float* Wc3   = (const float*)d_in[5];
    const float* Wfw   = (const float*)d_in[6];
    const float* Wfw_g = (const float*)d_in[7];
    const float* Wih1  = (const float*)d_in[8];
    const float* Whh1  = (const float*)d_in[9];
    const float* Wih2  = (const float*)d_in[10];
    const float* Whh2  = (const float*)d_in[11];
    const float* Wih3  = (const float*)d_in[12];
    const float* Whh3  = (const float*)d_in[13];
    const float* Wg1   = (const float*)d_in[14];
    const float* Wg2   = (const float*)d_in[15];
    const float* Wg3   = (const float*)d_in[16];
    const float* Wsg   = (const float*)d_in[17];
    const float* Wsd   = (const float*)d_in[18];
    const float* Wout  = (const float*)d_in[19];
    float* outp = (float*)d_out;

    static bool attr_set = false;
    if (!attr_set) {
        cudaFuncSetAttribute(fargan_kernel,
                             cudaFuncAttributeMaxDynamicSharedMemorySize, DYN_BYTES);
        attr_set = true;
    }

    convert_wsd_kernel<<<(128 * 320 + 255) / 256, 256>>>(Wsd);
    build_x_kernel<<<NBT, 64>>>(feats, glob);
    gemm_tanh_kernel<<<dim3(4, 100), 256>>>(Wc1, 0, 256, 256);
    gemm_tanh_kernel<<<dim3(4, 100), 256>>>(Wc2, 1, 256, 256);
    gemm_tanh_kernel<<<dim3(8, 100), 256>>>(Wc3, 2, 512, 256);
    fwpre_kernel<<<NBT, 256>>>(Wfw);
    fargan_kernel<<<BATCH / 2, NTH, DYN_BYTES>>>(prev0,
                                  Wfw, Wfw_g,
                                  Wih1, Whh1, Wih2, Whh2, Wih3, Whh3,
                                  Wg1, Wg2, Wg3, Wsg, Wout, outp);
}

// round 9
// speedup vs baseline: 2.3791x; 1.6235x over previous
#include <cuda_runtime.h>
#include <cuda_fp16.h>
#include <math.h>

#define S       64
#define LPREV   512
#define NF      193
#define NFRAMES 100
#define BATCH   64
#define NTH     512
#define NBT     (BATCH * NFRAMES)   // 6400

// ---------------- scratch (static device allocations) ----------------
__device__ float  g_X [NBT * 256];
__device__ float  g_H1[NBT * 256];
__device__ float  g_H2[NBT * 256];
__device__ float  g_C [NBT * 512];
__device__ float  g_fwpre[NBT * 4 * 64];
__device__ int    g_period[NBT];
__device__ __half g_hWsd[128 * 320];

__device__ __forceinline__ float sigm(float x)   { return __fdividef(1.f, 1.f + __expf(-x)); }
__device__ __forceinline__ float tanh_f(float x) { return fmaf(2.f, __fdividef(1.f, 1.f + __expf(-2.f * x)), -1.f); }
__device__ __forceinline__ float red8(float v) {
    v += __shfl_xor_sync(0xffffffffu, v, 1);
    v += __shfl_xor_sync(0xffffffffu, v, 2);
    v += __shfl_xor_sync(0xffffffffu, v, 4);
    return v;
}
// dot of 8 fp16 weights (one uint4) with 8 fp32 inputs (two float4)
__device__ __forceinline__ float dot8h(uint4 u, float4 xa, float4 xb) {
    float2 f0 = __half22float2(*reinterpret_cast<__half2*>(&u.x));
    float2 f1 = __half22float2(*reinterpret_cast<__half2*>(&u.y));
    float2 f2 = __half22float2(*reinterpret_cast<__half2*>(&u.z));
    float2 f3 = __half22float2(*reinterpret_cast<__half2*>(&u.w));
    float a = fmaf(f0.x, xa.x, f0.y * xa.y);
    a = fmaf(f1.x, xa.z, a); a = fmaf(f1.y, xa.w, a);
    a = fmaf(f2.x, xb.x, a); a = fmaf(f2.y, xb.y, a);
    a = fmaf(f3.x, xb.z, a); a = fmaf(f3.y, xb.w, a);
    return a;
}
// pack 8 consecutive fp32 -> uint4 of 8 fp16
__device__ __forceinline__ uint4 pack8(const float* __restrict__ s) {
    union { uint4 u; __half2 h[4]; } r;
    r.h[0] = __floats2half2_rn(__ldg(&s[0]), __ldg(&s[1]));
    r.h[1] = __floats2half2_rn(__ldg(&s[2]), __ldg(&s[3]));
    r.h[2] = __floats2half2_rn(__ldg(&s[4]), __ldg(&s[5]));
    r.h[3] = __floats2half2_rn(__ldg(&s[6]), __ldg(&s[7]));
    return r.u;
}

// ---------------- prep kernels ----------------
__global__ void convert_wsd_kernel(const float* __restrict__ Wsd)
{
    int i = blockIdx.x * blockDim.x + threadIdx.x;
    if (i < 128 * 320) g_hWsd[i] = __float2half(Wsd[i]);
}

__global__ void build_x_kernel(const float* __restrict__ feats,
                               const float* __restrict__ glob)
{
    const int bt = blockIdx.x;
    const int b = bt / NFRAMES, t = bt % NFRAMES;
    const float* fb = feats + (long)b * NF * NFRAMES;
    for (int i = threadIdx.x; i < 192; i += blockDim.x)
        g_X[bt * 256 + i] = fb[i * NFRAMES + t];
    for (int i = threadIdx.x; i < 64; i += blockDim.x)
        g_X[bt * 256 + 192 + i] = glob[b * 64 + i];
    if (threadIdx.x == 0)
        g_period[bt] = (int)lrintf(fb[192 * NFRAMES + t]);
}

// C[M,N] = tanh(A[M,K] @ W[N,K]^T); tiles 64x64x64
__global__ __launch_bounds__(256)
void gemm_tanh_kernel(const float* __restrict__ Wt, int layer, int N, int K)
{
    const float* A = (layer == 0) ? g_X : (layer == 1) ? g_H1 : g_H2;
    float*       C = (layer == 0) ? g_H1 : (layer == 1) ? g_H2 : g_C;

    __shared__ float As[64][68];
    __shared__ float Ws[64][68];

    const int tid = threadIdx.x;
    const int m0 = blockIdx.y * 64, n0 = blockIdx.x * 64;
    const int lr = tid >> 2, lc = tid & 3;
    const int ty = tid >> 4, tx = tid & 15;

    float acc[4][4] = {};

    for (int k0 = 0; k0 < K; k0 += 64) {
        const float4* Arow = (const float4*)(A  + (long)(m0 + lr) * K + k0);
        const float4* Wrow = (const float4*)(Wt + (long)(n0 + lr) * K + k0);
        #pragma unroll
        for (int jj = 0; jj < 4; jj++) {
            float4 av = __ldg(&Arow[lc * 4 + jj]);
            float4 wv = __ldg(&Wrow[lc * 4 + jj]);
            int kk = lc * 16 + jj * 4;
            As[kk + 0][lr] = av.x; As[kk + 1][lr] = av.y;
            As[kk + 2][lr] = av.z; As[kk + 3][lr] = av.w;
            Ws[kk + 0][lr] = wv.x; Ws[kk + 1][lr] = wv.y;
            Ws[kk + 2][lr] = wv.z; Ws[kk + 3][lr] = wv.w;
        }
        __syncthreads();
        #pragma unroll
        for (int kk = 0; kk < 64; kk++) {
            float4 a = *(const float4*)&As[kk][ty * 4];
            float4 w = *(const float4*)&Ws[kk][tx * 4];
            acc[0][0] = fmaf(a.x, w.x, acc[0][0]); acc[0][1] = fmaf(a.x, w.y, acc[0][1]);
            acc[0][2] = fmaf(a.x, w.z, acc[0][2]); acc[0][3] = fmaf(a.x, w.w, acc[0][3]);
            acc[1][0] = fmaf(a.y, w.x, acc[1][0]); acc[1][1] = fmaf(a.y, w.y, acc[1][1]);
            acc[1][2] = fmaf(a.y, w.z, acc[1][2]); acc[1][3] = fmaf(a.y, w.w, acc[1][3]);
            acc[2][0] = fmaf(a.z, w.x, acc[2][0]); acc[2][1] = fmaf(a.z, w.y, acc[2][1]);
            acc[2][2] = fmaf(a.z, w.z, acc[2][2]); acc[2][3] = fmaf(a.z, w.w, acc[2][3]);
            acc[3][0] = fmaf(a.w, w.x, acc[3][0]); acc[3][1] = fmaf(a.w, w.y, acc[3][1]);
            acc[3][2] = fmaf(a.w, w.z, acc[3][2]); acc[3][3] = fmaf(a.w, w.w, acc[3][3]);
        }
        __syncthreads();
    }
    #pragma unroll
    for (int i = 0; i < 4; i++)
        #pragma unroll
        for (int j = 0; j < 4; j++)
            C[(long)(m0 + ty * 4 + i) * N + n0 + tx * 4 + j] = tanh_f(acc[i][j]);
}

// fwpre[bt][k][j] = Wfw[j,0:128] @ feat2s(bt,k) + Wfw[j,260:388] @ sfw(bt,k)
__global__ __launch_bounds__(256)
void fwpre_kernel(const float* __restrict__ Wfw)
{
    const int bt = blockIdx.x;
    const int t  = bt % NFRAMES;
    const int tid = threadIdx.x;
    __shared__ float sc[512], sp[512];
    for (int i = tid; i < 512; i += 256) {
        sc[i] = g_C[(long)bt * 512 + i];
        sp[i] = (t > 0) ? g_C[(long)(bt - 1) * 512 + i] : 0.f;
    }
    __syncthreads();
    const int p = tid & 3, row = tid >> 2;
    const float* wr = Wfw + row * 388;
    #pragma unroll
    for (int k = 0; k < 4; k++) {
        const float* sfw = (k == 0) ? sp : sc;
        const int ksf = (k == 0) ? 3 : (k - 1);
        float acc = 0.f;
        #pragma unroll 8
        for (int mm = 0; mm < 32; mm++) {
            int m = p * 32 + mm;
            acc = fmaf(__ldg(&wr[m]),       sc[4 * m + k],    acc);
            acc = fmaf(__ldg(&wr[260 + m]), sfw[4 * m + ksf], acc);
        }
        acc += __shfl_xor_sync(0xffffffffu, acc, 1);
        acc += __shfl_xor_sync(0xffffffffu, acc, 2);
        if (p == 0) g_fwpre[((long)bt * 4 + k) * 64 + row] = acc;
    }
}

// ---------------- serial recurrence ----------------

#define DYN_H16   (3 * 192 * 128 + 3 * 192 * 64)   // Wih x3 + Whh x3 = 110592 halfs
#define DYN_BYTES (DYN_H16 * 2)                    // 221184 B

__global__ __launch_bounds__(NTH, 1)
void fargan_kernel(const float* __restrict__ prev0,
                   const float* __restrict__ Wfw,     // (64,388)
                   const float* __restrict__ Wfw_g,   // (64,64)
                   const float* __restrict__ Wih1,    // (192,128)
                   const float* __restrict__ Whh1,    // (192,64)
                   const float* __restrict__ Wih2,
                   const float* __restrict__ Whh2,
                   const float* __restrict__ Wih3,
                   const float* __restrict__ Whh3,
                   const float* __restrict__ Wg1,     // (64,64)
                   const float* __restrict__ Wg2,
                   const float* __restrict__ Wg3,
                   const float* __restrict__ Wsg,     // (128,128)
                   const float* __restrict__ Wout,    // (64,128)
                   float* __restrict__ outp)          // (B, 25600)
{
    const int b   = blockIdx.x;
    const int tid = threadIdx.x;
    const int p   = tid & 7;        // 8 threads per row
    const int r0  = tid >> 3;       // 64 rows per pass

    extern __shared__ __half dynh[];
    __half* sWih = dynh;                 // 3 x 192 x 128
    __half* sWhh = dynh + 3 * 192 * 128; // 3 x 192 x 64

    __shared__ __align__(16) float ring[LPREV];
    __shared__ __align__(16) float st[2][3][S];      // double-buffered GRU states
    __shared__ __align__(16) float subin[136];       // [prev_sub(64) | lookback(68) | pad(4)]
    __shared__ __align__(16) float fwv[S];
    __shared__ __align__(16) float xcat[2 * S];
    __shared__ __align__(16) float skip[5 * S];      // [o1|o2|o3|fw|psub]
    __shared__ __align__(16) float sdv[2 * S];
    __shared__ __align__(16) float sov[2 * S];
    __shared__ __align__(16) float fwp4[256];
    __shared__ int period_sh;

    // ---- one-time: stage Wih / Whh as fp16 into smem ----
    {
        const float* src[3] = { Wih1, Wih2, Wih3 };
        #pragma unroll
        for (int m = 0; m < 3; m++)
            for (int i = tid; i < 192 * 128; i += NTH)
                sWih[m * 192 * 128 + i] = __float2half(__ldg(&src[m][i]));
        const float* srh[3] = { Whh1, Whh2, Whh3 };
        #pragma unroll
        for (int m = 0; m < 3; m++)
            for (int i = tid; i < 192 * 64; i += NTH)
                sWhh[m * 192 * 64 + i] = __float2half(__ldg(&srh[m][i]));
    }

    // ---- persistent register weight caches ----
    // Wfw2: cols [128,264) of Wfw, row r0, 17 consecutive floats per thread (fp32)
    float rfw2[17];
    #pragma unroll
    for (int i = 0; i < 17; i++) {
        int col = p * 17 + i;
        rfw2[i] = (col < 132) ? __ldg(&Wfw[r0 * 388 + 128 + col]) : 0.f;
    }
    // gates (Wg1,Wg2,Wg3,Wfwg): 64x64 fp16, chunk p of 8 per row
    uint4 rgate[4];
    {
        const float* gsrc[4] = { Wg1, Wg2, Wg3, Wfw_g };
        #pragma unroll
        for (int m = 0; m < 4; m++) rgate[m] = pack8(gsrc[m] + r0 * 64 + 8 * p);
    }
    // Wsg: 128x128 fp16, rows r0 and r0+64, chunks p and p+8
    uint4 rsgh[2][2];
    #pragma unroll
    for (int it = 0; it < 2; it++) {
        rsgh[it][0] = pack8(Wsg + (r0 + 64 * it) * 128 + 8 * p);
        rsgh[it][1] = pack8(Wsg + (r0 + 64 * it) * 128 + 8 * (p + 8));
    }
    // Wout: 64x128 fp16, row r0, chunks p and p+8
    uint4 routh[2];
    routh[0] = pack8(Wout + r0 * 128 + 8 * p);
    routh[1] = pack8(Wout + r0 * 128 + 8 * (p + 8));

    // Wsd chunk pointers: per part m (0..4), thread covers rows r0 / r0+64, cols [64m+8p, +8)
    const uint4* wsd0 = (const uint4*)(g_hWsd + r0 * 320) + p;         // + 8*m
    const uint4* wsd1 = (const uint4*)(g_hWsd + (r0 + 64) * 320) + p;  // + 8*m

    // ---- init state ----
    for (int i = tid; i < LPREV; i += NTH) ring[i] = prev0[b * LPREV + i];
    if (tid < 3 * S) st[0][tid >> 6][tid & 63] = 0.f;
    if (tid >= 132 && tid < 136) subin[tid] = 0.f;
    int head = 0;
    int pb = 0;
    __syncthreads();

    for (int tf = 0; tf < NFRAMES; tf++) {
        const int bt = b * NFRAMES + tf;
        // ---- frame top: stage fwpre for all 4 subframes + period ----
        if (tid < 256) fwp4[tid] = __ldg(&g_fwpre[(long)bt * 256 + tid]);
        if (tid == 0) period_sh = __ldg(&g_period[bt]);
        __syncthreads();
        const int period = period_sh;

        for (int k = 0; k < 4; k++) {
            float sd0 = 0.f, sd1 = 0.f;   // incremental Wsd @ skip accumulators

            // ---- A: build [prev_sub | lookback], seed tails ----
            if (tid < 132) {
                if (tid < 64) {
                    float v = ring[(head + 448 + tid) & 511];
                    subin[tid] = v;
                    skip[256 + tid] = v;
                    xcat[64 + tid] = v;
                } else {
                    int i = tid - 64;
                    int idx = LPREV - period + i - 2;
                    if (idx >= LPREV) idx -= period;
                    subin[tid] = ring[(head + idx) & 511];
                }
            }
            __syncthreads();

            // ---- B: fwraw = tanh(Wfw2 @ subin + fwpre)  [+ Wsd psub part]
            float fwreg;
            {
                uint4 w0 = __ldg(wsd0 + 32), w1 = __ldg(wsd1 + 32);   // part m=4 (psub)
                float a = 0.f;
                #pragma unroll
                for (int i = 0; i < 17; i++)
                    a = fmaf(rfw2[i], subin[p * 17 + i], a);
                fwreg = tanh_f(red8(a) + fwp4[k * 64 + r0]);
                if (p == 0) fwv[r0] = fwreg;
                const float4* xs = (const float4*)(skip + 256);
                sd0 += dot8h(w0, xs[2 * p], xs[2 * p + 1]);
                sd1 += dot8h(w1, xs[2 * p], xs[2 * p + 1]);
            }
            __syncthreads();

            // ---- C: fw = fwraw * sigm(Wfwg @ fwv)
            {
                const float4* x = (const float4*)fwv;
                float acc = red8(dot8h(rgate[3], x[2 * p], x[2 * p + 1]));
                fwreg = fwreg * sigm(acc);
                if (p == 0) { skip[192 + r0] = fwreg; xcat[r0] = fwreg; }
            }
            __syncthreads();

            // ---- 3 x (GRU fused + GLU fused), weights in smem fp16 ----
            #pragma unroll
            for (int L = 0; L < 3; L++) {
                const __half* WI = sWih + L * 192 * 128;
                const __half* WH = sWhh + L * 192 * 64;
                const float* sto = st[pb][L];
                float* stn = st[pb ^ 1][L];
                float streg;
                {
                    // Wsd part for this stage: L=0 -> fw (m=3), L=1 -> o1 (m=0), L=2 -> o2 (m=1)
                    const int m = (L == 0) ? 3 : (L - 1);
                    uint4 w0 = __ldg(wsd0 + 8 * m), w1 = __ldg(wsd1 + 8 * m);

                    const float4* x = (const float4*)xcat;
                    float4 xa0 = x[2 * p], xa1 = x[2 * p + 1];
                    float4 xb0 = x[2 * p + 16], xb1 = x[2 * p + 17];
                    float4 sv0 = ((const float4*)sto)[2 * p], sv1 = ((const float4*)sto)[2 * p + 1];
                    float gi[3], gh[3];
                    #pragma unroll
                    for (int it = 0; it < 3; it++) {
                        const uint4* wi = (const uint4*)(WI + (r0 + (it << 6)) * 128);
                        float a = dot8h(wi[p], xa0, xa1) + dot8h(wi[p + 8], xb0, xb1);
                        gi[it] = red8(a);
                        const uint4* wh = (const uint4*)(WH + (r0 + (it << 6)) * 64);
                        gh[it] = red8(dot8h(wh[p], sv0, sv1));
                    }
                    float r = sigm(gi[0] + gh[0]);
                    float z = sigm(gi[1] + gh[1]);
                    float n = tanh_f(gi[2] + r * gh[2]);
                    streg = (1.f - z) * n + z * sto[r0];
                    if (p == 0) stn[r0] = streg;

                    const float4* xm = (const float4*)(skip + 64 * m);
                    sd0 += dot8h(w0, xm[2 * p], xm[2 * p + 1]);
                    sd1 += dot8h(w1, xm[2 * p], xm[2 * p + 1]);
                }
                __syncthreads();
                {
                    const float4* x = (const float4*)stn;
                    float acc = red8(dot8h(rgate[L], x[2 * p], x[2 * p + 1]));
                    float v = streg * sigm(acc);
                    if (p == 0) {
                        skip[64 * L + r0] = v;
                        if (L < 2) xcat[r0] = v;
                    }
                }
                __syncthreads();
            }

            // ---- J (mini): add o3 part, finalize sdv ----
            float sdva[2];
            {
                uint4 w0 = __ldg(wsd0 + 16), w1 = __ldg(wsd1 + 16);   // part m=2 (o3)
                const float4* xm = (const float4*)(skip + 128);
                sd0 += dot8h(w0, xm[2 * p], xm[2 * p + 1]);
                sd1 += dot8h(w1, xm[2 * p], xm[2 * p + 1]);
                sdva[0] = tanh_f(red8(sd0));
                sdva[1] = tanh_f(red8(sd1));
                if (p == 0) { sdv[r0] = sdva[0]; sdv[64 + r0] = sdva[1]; }
            }
            __syncthreads();

            // ---- K: sov = sdv * sigm(Wsg @ sdv)   (register fp16)
            {
                const float4* x = (const float4*)sdv;
                float4 xa0 = x[2 * p], xa1 = x[2 * p + 1];
                float4 xb0 = x[2 * p + 16], xb1 = x[2 * p + 17];
                #pragma unroll
                for (int it = 0; it < 2; it++) {
                    float acc = dot8h(rsgh[it][0], xa0, xa1) + dot8h(rsgh[it][1], xb0, xb1);
                    acc = red8(acc);
                    if (p == 0) sov[r0 + 64 * it] = sdva[it] * sigm(acc);
                }
            }
            __syncthreads();

            // ---- L: out = tanh(Wout @ sov); emit + ring update   (register fp16)
            {
                const float4* x = (const float4*)sov;
                float acc = dot8h(routh[0], x[2 * p], x[2 * p + 1])
                          + dot8h(routh[1], x[2 * p + 16], x[2 * p + 17]);
                float out = tanh_f(red8(acc));
                if (p == 0) {
                    outp[(long)b * (NFRAMES * 4 * S) + tf * (4 * S) + k * S + r0] = out;
                    ring[(head + r0) & 511] = out;
                }
            }
            head = (head + 64) & 511;
            pb ^= 1;
            __syncthreads();
        }
    }
}

extern "C" void kernel_launch(void* const* d_in, const int* in_sizes, int n_in,
                              void* d_out, int out_size)
{
    const float* feats = (const float*)d_in[0];
    const float* glob  = (const float*)d_in[1];
    const float* prev0 = (const float*)d_in[2];
    const float* Wc1   = (const float*)d_in[3];
    const float* Wc2   = (const float*)d_in[4];
    const float* Wc3   = (const float*)d_in[5];
    const float* Wfw   = (const float*)d_in[6];
    const float* Wfw_g = (const float*)d_in[7];
    const float* Wih1  = (const float*)d_in[8];
    const float* Whh1  = (const float*)d_in[9];
    const float* Wih2  = (const float*)d_in[10];
    const float* Whh2  = (const float*)d_in[11];
    const float* Wih3  = (const float*)d_in[12];
    const float* Whh3  = (const float*)d_in[13];
    const float* Wg1   = (const float*)d_in[14];
    const float* Wg2   = (const float*)d_in[15];
    const float* Wg3   = (const float*)d_in[16];
    const float* Wsg   = (const float*)d_in[17];
    const float* Wsd   = (const float*)d_in[18];
    const float* Wout  = (const float*)d_in[19];
    float* outp = (float*)d_out;

    static bool attr_set = false;
    if (!attr_set) {
        cudaFuncSetAttribute(fargan_kernel,
                             cudaFuncAttributeMaxDynamicSharedMemorySize, DYN_BYTES);
        attr_set = true;
    }

    convert_wsd_kernel<<<(128 * 320 + 255) / 256, 256>>>(Wsd);
    build_x_kernel<<<NBT, 64>>>(feats, glob);
    gemm_tanh_kernel<<<dim3(4, 100), 256>>>(Wc1, 0, 256, 256);
    gemm_tanh_kernel<<<dim3(4, 100), 256>>>(Wc2, 1, 256, 256);
    gemm_tanh_kernel<<<dim3(8, 100), 256>>>(Wc3, 2, 512, 256);
    fwpre_kernel<<<NBT, 256>>>(Wfw);
    fargan_kernel<<<BATCH, NTH, DYN_BYTES>>>(prev0,
                                  Wfw, Wfw_g,
                                  Wih1, Whh1, Wih2, Whh2, Wih3, Whh3,
                                  Wg1, Wg2, Wg3, Wsg, Wout, outp);
}